// round 1
// baseline (speedup 1.0000x reference)
#include <cuda_runtime.h>

#define BB 4
#define CIN 256
#define CO 8
#define HH 64          // input spatial
#define SS 512         // resize_shape
#define SMDIM 128      // pooled spatial (SS / 2^DEPTH)
#define QQ 4096        // (SS/P)^2
#define P2 64          // P*P
#define KK 256         // Lh*Lh (attention last dim)

// Scratch (static device allocations are allowed)
__device__ float g_y[BB * CO * HH * HH];          // conv output, small
__device__ float g_fm[BB * CO * SMDIM * SMDIM];   // pooled onehot means
__device__ float g_corr[BB * CO * QQ * P2];       // 33.5 MB

// ---------------------------------------------------------------------------
// K1: 1x1 conv  y[b,o,h,w] = sum_c x[b,c,h,w]*w[o,c] + b[o]
// Block = 256 threads = 64 hw-positions x 4 channel-quarters.
// ---------------------------------------------------------------------------
__global__ void k_conv(const float* __restrict__ x, const float* __restrict__ w,
                       const float* __restrict__ bias) {
    __shared__ float ws[CO * CIN];
    __shared__ float sb[CO];
    __shared__ float red[4][64][CO];
    for (int i = threadIdx.x; i < CO * CIN; i += blockDim.x) ws[i] = w[i];
    if (threadIdx.x < CO) sb[threadIdx.x] = bias[threadIdx.x];
    __syncthreads();

    int t = threadIdx.x;
    int pos_local = t & 63;          // 0..63
    int cq = t >> 6;                 // 0..3 channel quarter
    int gpos = blockIdx.x * 64 + pos_local;   // b*4096 + hw
    int b = gpos >> 12;
    int hw = gpos & 4095;

    const float* xp = x + (size_t)b * CIN * 4096 + hw + (size_t)cq * 64 * 4096;
    float acc[CO];
#pragma unroll
    for (int o = 0; o < CO; o++) acc[o] = 0.0f;
#pragma unroll 8
    for (int c = 0; c < 64; c++) {
        float xv = xp[(size_t)c * 4096];
        const float* wr = &ws[(cq * 64 + c)];
#pragma unroll
        for (int o = 0; o < CO; o++) acc[o] = fmaf(xv, wr[o * CIN], acc[o]);
    }
#pragma unroll
    for (int o = 0; o < CO; o++) red[cq][pos_local][o] = acc[o];
    __syncthreads();

    // reduce 4 quarters: 64 pos * 8 out = 512 values, 256 threads do 2 each
    for (int i = t; i < 64 * CO; i += 256) {
        int pl = i >> 3, o = i & 7;
        float v = red[0][pl][o] + red[1][pl][o] + red[2][pl][o] + red[3][pl][o] + sb[o];
        int gp = blockIdx.x * 64 + pl;
        int bb = gp >> 12, hw2 = gp & 4095;
        g_y[(size_t)bb * CO * 4096 + (size_t)o * 4096 + hw2] = v;
    }
}

// ---------------------------------------------------------------------------
// bilinear coefficient (align_corners=True), matches linspace(0, 63, 512)
// ---------------------------------------------------------------------------
__device__ __forceinline__ void lerp_coef(int s, int& lo, int& hi, float& f) {
    float pos = (s == SS - 1) ? (float)(HH - 1)
                              : (float)s * ((float)(HH - 1) / (float)(SS - 1));
    lo = (int)pos;                 // floor (pos >= 0)
    f = pos - (float)lo;
    hi = lo + 1;
    if (hi > HH - 1) hi = HH - 1;
}

__device__ __forceinline__ float bilerp(const float* __restrict__ yc,
                                        int sl, int sh, float sf,
                                        int tl, int th, float tf) {
    // interpolate along w first, then h (matches einsum contraction order)
    float v0 = yc[sl * HH + tl] * (1.0f - tf) + yc[sl * HH + th] * tf;
    float v1 = yc[sh * HH + tl] * (1.0f - tf) + yc[sh * HH + th] * tf;
    return v0 * (1.0f - sf) + v1 * sf;
}

// ---------------------------------------------------------------------------
// K2: upsample -> argmax -> 4x4 mean pool of onehot. One thread per pooled cell.
// ---------------------------------------------------------------------------
__global__ void k_fm() {
    int idx = blockIdx.x * blockDim.x + threadIdx.x;   // b*16384 + i*128 + j
    int b = idx >> 14;
    int ij = idx & 16383;
    int i = ij >> 7, j = ij & 127;
    int cnt[CO];
#pragma unroll
    for (int c = 0; c < CO; c++) cnt[c] = 0;
    const float* yb = g_y + (size_t)b * CO * 4096;
#pragma unroll
    for (int di = 0; di < 4; di++) {
        int s = i * 4 + di;
        int sl, sh; float sf; lerp_coef(s, sl, sh, sf);
#pragma unroll
        for (int dj = 0; dj < 4; dj++) {
            int t = j * 4 + dj;
            int tl, th; float tf; lerp_coef(t, tl, th, tf);
            float best = -1e30f; int bi = 0;
#pragma unroll
            for (int c = 0; c < CO; c++) {
                float v = bilerp(yb + c * 4096, sl, sh, sf, tl, th, tf);
                if (v > best) { best = v; bi = c; }   // strict >: first-index tie-break
            }
            cnt[bi]++;
        }
    }
    float* fp = g_fm + (size_t)b * CO * 16384 + ij;
#pragma unroll
    for (int c = 0; c < CO; c++) fp[(size_t)c * 16384] = (float)cnt[c] * (1.0f / 16.0f);
}

// ---------------------------------------------------------------------------
// K3: batched GEMM  corr[q,p] = (A[q,:] . unf[p,:]) / (nz[q]+1e-5)
// per block: 64 q-rows x 64 p-cols, K=256 in 4 chunks of 64.
// Fused: nonzero count per row (warp ballot) + optional attentions copy-out.
// ---------------------------------------------------------------------------
__global__ void k_gemm(const float* __restrict__ att, float* __restrict__ att_out,
                       int do_copy) {
    __shared__ __align__(16) float As[64][68];   // [k][q]
    __shared__ __align__(16) float Us[64][68];   // [k][p]
    __shared__ int   s_cnt[64];
    __shared__ float s_scale[64];

    int t = threadIdx.x;
    int q0 = blockIdx.x * 64;
    int bc = blockIdx.y;                          // b*8 + c
    if (t < 64) s_cnt[t] = 0;
    __syncthreads();

    const float* Ab = att + (size_t)bc * QQ * KK + (size_t)q0 * KK;
    float*       Ob = att_out + (size_t)bc * QQ * KK + (size_t)q0 * KK;
    const float* Fb = g_fm + (size_t)bc * 16384;

    int tq = t >> 4;        // 0..15 -> 4 q rows
    int tp = t & 15;        // 0..15 -> 4 p cols
    float acc[4][4];
#pragma unroll
    for (int a = 0; a < 4; a++)
#pragma unroll
        for (int bq = 0; bq < 4; bq++) acc[a][bq] = 0.0f;

    for (int kc = 0; kc < 4; kc++) {
        // load A chunk (coalesced), count nonzeros, optional copy-out
#pragma unroll
        for (int i = 0; i < 16; i++) {
            int idx = i * 256 + t;
            int r = idx >> 6, kk = idx & 63;       // r uniform per warp
            size_t go = (size_t)r * KK + kc * 64 + kk;
            float v = Ab[go];
            if (do_copy) Ob[go] = v;
            unsigned m = __ballot_sync(0xffffffffu, v != 0.0f);
            if ((t & 31) == 0) atomicAdd(&s_cnt[r], __popc(m));
            As[kk][r] = v;
        }
        // load unf chunk: unf[p][k] = fm[(k/16)*8 + p/8][(k%16)*8 + p%8]
#pragma unroll
        for (int i = 0; i < 16; i++) {
            int idx = i * 256 + t;
            int kk = idx >> 6, p = idx & 63;
            int k = kc * 64 + kk;
            int lh = k >> 4, lw = k & 15;
            int pi = p >> 3, qi = p & 7;
            Us[kk][p] = Fb[(lh * 8 + pi) * 128 + (lw * 8 + qi)];
        }
        __syncthreads();

#pragma unroll 4
        for (int kk = 0; kk < 64; kk++) {
            float4 a = *(const float4*)&As[kk][tq << 2];
            float4 u = *(const float4*)&Us[kk][tp << 2];
            acc[0][0] = fmaf(a.x, u.x, acc[0][0]);
            acc[0][1] = fmaf(a.x, u.y, acc[0][1]);
            acc[0][2] = fmaf(a.x, u.z, acc[0][2]);
            acc[0][3] = fmaf(a.x, u.w, acc[0][3]);
            acc[1][0] = fmaf(a.y, u.x, acc[1][0]);
            acc[1][1] = fmaf(a.y, u.y, acc[1][1]);
            acc[1][2] = fmaf(a.y, u.z, acc[1][2]);
            acc[1][3] = fmaf(a.y, u.w, acc[1][3]);
            acc[2][0] = fmaf(a.z, u.x, acc[2][0]);
            acc[2][1] = fmaf(a.z, u.y, acc[2][1]);
            acc[2][2] = fmaf(a.z, u.z, acc[2][2]);
            acc[2][3] = fmaf(a.z, u.w, acc[2][3]);
            acc[3][0] = fmaf(a.w, u.x, acc[3][0]);
            acc[3][1] = fmaf(a.w, u.y, acc[3][1]);
            acc[3][2] = fmaf(a.w, u.z, acc[3][2]);
            acc[3][3] = fmaf(a.w, u.w, acc[3][3]);
        }
        __syncthreads();
    }

    if (t < 64) s_scale[t] = 1.0f / ((float)s_cnt[t] + 1e-5f);
    __syncthreads();

    float* Cb = g_corr + (size_t)bc * QQ * P2 + (size_t)q0 * P2;
#pragma unroll
    for (int i = 0; i < 4; i++) {
        float sc = s_scale[tq * 4 + i];
        float4 v = make_float4(acc[i][0] * sc, acc[i][1] * sc,
                               acc[i][2] * sc, acc[i][3] * sc);
        *(float4*)&Cb[(size_t)(tq * 4 + i) * P2 + (tp << 2)] = v;
    }
}

// ---------------------------------------------------------------------------
// K4: out[b,c,s,t] = log_softmax_c( (corr[b,c,q,p]+1) * y_up[b,c,s,t] )
// with q = (s/8)*64 + t/8, p = (s%8)*8 + t%8
// ---------------------------------------------------------------------------
__global__ void k_out(float* __restrict__ out) {
    int idx = blockIdx.x * blockDim.x + threadIdx.x;  // b*262144 + s*512 + t
    int b = idx >> 18;
    int st = idx & 262143;
    int s = st >> 9, t = st & 511;
    int sl, sh; float sf; lerp_coef(s, sl, sh, sf);
    int tl, th; float tf; lerp_coef(t, tl, th, tf);
    int q = (s >> 3) * 64 + (t >> 3);
    int p = (s & 7) * 8 + (t & 7);

    const float* yb = g_y + (size_t)b * CO * 4096;
    const float* cb = g_corr + (size_t)(b * CO) * QQ * P2 + (size_t)q * P2 + p;

    float logit[CO];
    float mx = -1e30f;
#pragma unroll
    for (int c = 0; c < CO; c++) {
        float yv = bilerp(yb + c * 4096, sl, sh, sf, tl, th, tf);
        float corrv = cb[(size_t)c * QQ * P2];
        float l = (corrv + 1.0f) * yv;
        logit[c] = l;
        mx = fmaxf(mx, l);
    }
    float sum = 0.0f;
#pragma unroll
    for (int c = 0; c < CO; c++) sum += __expf(logit[c] - mx);
    float lse = mx + __logf(sum);
    float* op = out + (size_t)b * CO * 262144 + st;
#pragma unroll
    for (int c = 0; c < CO; c++) op[(size_t)c * 262144] = logit[c] - lse;
}

// ---------------------------------------------------------------------------
extern "C" void kernel_launch(void* const* d_in, const int* in_sizes, int n_in,
                              void* d_out, int out_size) {
    const float* x    = (const float*)d_in[0];
    const float* att  = (const float*)d_in[1];
    const float* w    = (const float*)d_in[2];
    const float* bias = (const float*)d_in[3];
    float* out = (float*)d_out;

    const int OUT_ELEMS = BB * CO * SS * SS;   // 8388608
    const int ATT_ELEMS = BB * CO * QQ * KK;   // 33554432
    int do_copy = (out_size >= OUT_ELEMS + ATT_ELEMS) ? 1 : 0;
    float* att_out = out + OUT_ELEMS;

    k_conv<<<BB * HH * HH / 64, 256>>>(x, w, bias);
    k_fm<<<BB * SMDIM * SMDIM / 256, 256>>>();
    k_gemm<<<dim3(QQ / 64, BB * CO), 256>>>(att, att_out, do_copy);
    k_out<<<BB * SS * SS / 256, 256>>>(out);
}

// round 4
// speedup vs baseline: 1.2035x; 1.2035x over previous
#include <cuda_runtime.h>

#define BB 4
#define CIN 256
#define CO 8
#define HH 64          // input spatial
#define SS 512         // resize_shape
#define SMDIM 128      // pooled spatial (SS / 2^DEPTH)
#define QQ 4096        // (SS/P)^2
#define P2 64          // P*P
#define KK 256         // Lh*Lh (attention last dim)

// Scratch (static device allocations are allowed)
__device__ float g_y[BB * CO * HH * HH];          // conv output, small
__device__ float g_fm[BB * CO * SMDIM * SMDIM];   // pooled onehot means
__device__ float g_corr[BB * CO * QQ * P2];       // 33.5 MB

// ---------------------------------------------------------------------------
// K1: 1x1 conv  y[b,o,h,w] = sum_c x[b,c,h,w]*w[o,c] + b[o]
// ---------------------------------------------------------------------------
__global__ void k_conv(const float* __restrict__ x, const float* __restrict__ w,
                       const float* __restrict__ bias) {
    __shared__ float ws[CO * CIN];
    __shared__ float sb[CO];
    __shared__ float red[4][64][CO];
    for (int i = threadIdx.x; i < CO * CIN; i += blockDim.x) ws[i] = w[i];
    if (threadIdx.x < CO) sb[threadIdx.x] = bias[threadIdx.x];
    __syncthreads();

    int t = threadIdx.x;
    int pos_local = t & 63;
    int cq = t >> 6;
    int gpos = blockIdx.x * 64 + pos_local;
    int b = gpos >> 12;
    int hw = gpos & 4095;

    const float* xp = x + (size_t)b * CIN * 4096 + hw + (size_t)cq * 64 * 4096;
    float acc[CO];
#pragma unroll
    for (int o = 0; o < CO; o++) acc[o] = 0.0f;
#pragma unroll 8
    for (int c = 0; c < 64; c++) {
        float xv = xp[(size_t)c * 4096];
        const float* wr = &ws[(cq * 64 + c)];
#pragma unroll
        for (int o = 0; o < CO; o++) acc[o] = fmaf(xv, wr[o * CIN], acc[o]);
    }
#pragma unroll
    for (int o = 0; o < CO; o++) red[cq][pos_local][o] = acc[o];
    __syncthreads();

    for (int i = t; i < 64 * CO; i += 256) {
        int pl = i >> 3, o = i & 7;
        float v = red[0][pl][o] + red[1][pl][o] + red[2][pl][o] + red[3][pl][o] + sb[o];
        int gp = blockIdx.x * 64 + pl;
        int bb = gp >> 12, hw2 = gp & 4095;
        g_y[(size_t)bb * CO * 4096 + (size_t)o * 4096 + hw2] = v;
    }
}

// ---------------------------------------------------------------------------
// bilinear coefficient (align_corners=True)
// ---------------------------------------------------------------------------
__device__ __forceinline__ void lerp_coef(int s, int& lo, int& hi, float& f) {
    float pos = (s == SS - 1) ? (float)(HH - 1)
                              : (float)s * ((float)(HH - 1) / (float)(SS - 1));
    lo = (int)pos;
    f = pos - (float)lo;
    hi = lo + 1;
    if (hi > HH - 1) hi = HH - 1;
}

__device__ __forceinline__ float bilerp(const float* __restrict__ yc,
                                        int sl, int sh, float sf,
                                        int tl, int th, float tf) {
    float v0 = yc[sl * HH + tl] * (1.0f - tf) + yc[sl * HH + th] * tf;
    float v1 = yc[sh * HH + tl] * (1.0f - tf) + yc[sh * HH + th] * tf;
    return v0 * (1.0f - sf) + v1 * sf;
}

// ---------------------------------------------------------------------------
// K2: upsample -> argmax -> 4x4 mean pool of onehot
// ---------------------------------------------------------------------------
__global__ void k_fm() {
    int idx = blockIdx.x * blockDim.x + threadIdx.x;
    int b = idx >> 14;
    int ij = idx & 16383;
    int i = ij >> 7, j = ij & 127;
    int cnt[CO];
#pragma unroll
    for (int c = 0; c < CO; c++) cnt[c] = 0;
    const float* yb = g_y + (size_t)b * CO * 4096;
#pragma unroll
    for (int di = 0; di < 4; di++) {
        int s = i * 4 + di;
        int sl, sh; float sf; lerp_coef(s, sl, sh, sf);
#pragma unroll
        for (int dj = 0; dj < 4; dj++) {
            int t = j * 4 + dj;
            int tl, th; float tf; lerp_coef(t, tl, th, tf);
            float best = -1e30f; int bi = 0;
#pragma unroll
            for (int c = 0; c < CO; c++) {
                float v = bilerp(yb + c * 4096, sl, sh, sf, tl, th, tf);
                if (v > best) { best = v; bi = c; }
            }
            cnt[bi]++;
        }
    }
    float* fp = g_fm + (size_t)b * CO * 16384 + ij;
#pragma unroll
    for (int c = 0; c < CO; c++) fp[(size_t)c * 16384] = (float)cnt[c] * (1.0f / 16.0f);
}

// ---------------------------------------------------------------------------
// K3: batched GEMM with packed FFMA2 (fma.rn.f32x2), accumulator paired
// along K (lo = even k, hi = odd k; horizontal add at the end).
// Block tile: 128 q x 64 p, 256 threads, per-thread 8q x 4p (32 f32x2 accs).
// Smem layouts put the k-pair contiguous:
//   As[kp][q*2 + (k&1)]  (row 258 floats, padded)  -> compute loads broadcast
//   Us[kp][p*2 + (k&1)]  (row 130 floats, padded)  -> compute loads conflict-free
// Fused: per-row nonzero count (shfl reduce + smem atomics), att copy-out.
// ---------------------------------------------------------------------------
__global__ void __launch_bounds__(256) k_gemm(const float* __restrict__ att,
                                              float* __restrict__ att_out,
                                              int do_copy) {
    __shared__ __align__(16) float As[16][258];
    __shared__ __align__(16) float Us[16][130];
    __shared__ int   s_cnt[128];
    __shared__ float s_scale[128];

    int t = threadIdx.x;
    int q0 = blockIdx.x * 128;
    int bc = blockIdx.y;
    int tq = t >> 4;        // 0..15
    int tp = t & 15;        // 0..15
    int lane = t & 31;

    if (t < 128) s_cnt[t] = 0;
    __syncthreads();

    const float* Ab = att + (size_t)bc * QQ * KK + (size_t)q0 * KK;
    float*       Ob = att_out + (size_t)bc * QQ * KK + (size_t)q0 * KK;
    const float* Fb = g_fm + (size_t)bc * 16384;

    unsigned long long acc[8][4];
#pragma unroll
    for (int i = 0; i < 8; i++)
#pragma unroll
        for (int j = 0; j < 4; j++) acc[i][j] = 0ull;

    for (int kc = 0; kc < 8; kc++) {
        // ---- fill A chunk: 128 rows x 32 k (float4 per thread, 4 iters) ----
#pragma unroll
        for (int i = 0; i < 4; i++) {
            int slot = i * 256 + t;
            int r = slot >> 3;               // 0..127
            int c4 = (slot & 7) << 2;        // 0,4,...,28
            size_t go = (size_t)r * KK + kc * 32 + c4;
            float4 v = *(const float4*)(Ab + go);
            if (do_copy) *(float4*)(Ob + go) = v;
            int nz = (v.x != 0.0f) + (v.y != 0.0f) + (v.z != 0.0f) + (v.w != 0.0f);
            nz += __shfl_xor_sync(0xffffffffu, nz, 4);
            nz += __shfl_xor_sync(0xffffffffu, nz, 2);
            nz += __shfl_xor_sync(0xffffffffu, nz, 1);
            if ((lane & 7) == 0) atomicAdd(&s_cnt[r], nz);
            int kp = c4 >> 1;                // even
            *(float2*)&As[kp][r * 2]     = make_float2(v.x, v.y);
            *(float2*)&As[kp + 1][r * 2] = make_float2(v.z, v.w);
        }
        // ---- fill U chunk: 64 p x 32 k ----
#pragma unroll
        for (int i = 0; i < 8; i++) {
            int idx = i * 256 + t;
            int p = idx >> 5, k = idx & 31;
            int gk = kc * 32 + k;
            int lh = gk >> 4, lw = gk & 15;
            float v = Fb[(lh * 8 + (p >> 3)) * 128 + lw * 8 + (p & 7)];
            Us[k >> 1][p * 2 + (k & 1)] = v;
        }
        __syncthreads();

        // ---- compute: 16 k-pairs ----
#pragma unroll 4
        for (int kp = 0; kp < 16; kp++) {
            unsigned long long uu[4], aa[8];
#pragma unroll
            for (int j = 0; j < 4; j++)
                uu[j] = *(const unsigned long long*)&Us[kp][(tp + 16 * j) * 2];
#pragma unroll
            for (int i = 0; i < 8; i++)
                aa[i] = *(const unsigned long long*)&As[kp][(tq + 16 * i) * 2];
#pragma unroll
            for (int i = 0; i < 8; i++)
#pragma unroll
                for (int j = 0; j < 4; j++)
                    asm("fma.rn.f32x2 %0, %1, %2, %0;"
                        : "+l"(acc[i][j]) : "l"(aa[i]), "l"(uu[j]));
        }
        __syncthreads();
    }

    if (t < 128) s_scale[t] = 1.0f / ((float)s_cnt[t] + 1e-5f);
    __syncthreads();

    float* Cb = g_corr + (size_t)bc * QQ * P2 + (size_t)q0 * P2;
#pragma unroll
    for (int i = 0; i < 8; i++) {
        int ql = tq + 16 * i;
        float sc = s_scale[ql];
#pragma unroll
        for (int j = 0; j < 4; j++) {
            float lo = __uint_as_float((unsigned)acc[i][j]);
            float hi = __uint_as_float((unsigned)(acc[i][j] >> 32));
            Cb[(size_t)ql * P2 + tp + 16 * j] = (lo + hi) * sc;
        }
    }
}

// ---------------------------------------------------------------------------
// K4: out = log_softmax_c( (corr+1) * y_up )
// ---------------------------------------------------------------------------
__global__ void k_out(float* __restrict__ out) {
    int idx = blockIdx.x * blockDim.x + threadIdx.x;
    int b = idx >> 18;
    int st = idx & 262143;
    int s = st >> 9, t = st & 511;
    int sl, sh; float sf; lerp_coef(s, sl, sh, sf);
    int tl, th; float tf; lerp_coef(t, tl, th, tf);
    int q = (s >> 3) * 64 + (t >> 3);
    int p = (s & 7) * 8 + (t & 7);

    const float* yb = g_y + (size_t)b * CO * 4096;
    const float* cb = g_corr + (size_t)(b * CO) * QQ * P2 + (size_t)q * P2 + p;

    float logit[CO];
    float mx = -1e30f;
#pragma unroll
    for (int c = 0; c < CO; c++) {
        float yv = bilerp(yb + c * 4096, sl, sh, sf, tl, th, tf);
        float corrv = cb[(size_t)c * QQ * P2];
        float l = (corrv + 1.0f) * yv;
        logit[c] = l;
        mx = fmaxf(mx, l);
    }
    float sum = 0.0f;
#pragma unroll
    for (int c = 0; c < CO; c++) sum += __expf(logit[c] - mx);
    float lse = mx + __logf(sum);
    float* op = out + (size_t)b * CO * 262144 + st;
#pragma unroll
    for (int c = 0; c < CO; c++) op[(size_t)c * 262144] = logit[c] - lse;
}

// ---------------------------------------------------------------------------
extern "C" void kernel_launch(void* const* d_in, const int* in_sizes, int n_in,
                              void* d_out, int out_size) {
    const float* x    = (const float*)d_in[0];
    const float* att  = (const float*)d_in[1];
    const float* w    = (const float*)d_in[2];
    const float* bias = (const float*)d_in[3];
    float* out = (float*)d_out;

    const int OUT_ELEMS = BB * CO * SS * SS;   // 8388608
    const int ATT_ELEMS = BB * CO * QQ * KK;   // 33554432
    int do_copy = (out_size >= OUT_ELEMS + ATT_ELEMS) ? 1 : 0;
    float* att_out = out + OUT_ELEMS;

    k_conv<<<BB * HH * HH / 64, 256>>>(x, w, bias);
    k_fm<<<BB * SMDIM * SMDIM / 256, 256>>>();
    k_gemm<<<dim3(QQ / 128, BB * CO), 256>>>(att, att_out, do_copy);
    k_out<<<BB * SS * SS / 256, 256>>>(out);
}

// round 10
// speedup vs baseline: 1.4114x; 1.1728x over previous
#include <cuda_runtime.h>
#include <cuda_bf16.h>
#include <cstdint>

#define BB 4
#define CIN 256
#define CO 8
#define HH 64          // input spatial
#define SS 512         // resize_shape
#define SMDIM 128      // pooled spatial
#define QQ 4096
#define P2 64
#define KK 256

__device__ float g_y[BB * CO * HH * HH];
__device__ float g_fm[BB * CO * SMDIM * SMDIM];
__device__ float g_corr[BB * CO * QQ * P2];

// ---------------------------------------------------------------------------
// K1: 1x1 conv
// ---------------------------------------------------------------------------
__global__ void k_conv(const float* __restrict__ x, const float* __restrict__ w,
                       const float* __restrict__ bias) {
    __shared__ float ws[CO * CIN];
    __shared__ float sb[CO];
    __shared__ float red[4][64][CO];
    for (int i = threadIdx.x; i < CO * CIN; i += blockDim.x) ws[i] = w[i];
    if (threadIdx.x < CO) sb[threadIdx.x] = bias[threadIdx.x];
    __syncthreads();

    int t = threadIdx.x;
    int pos_local = t & 63;
    int cq = t >> 6;
    int gpos = blockIdx.x * 64 + pos_local;
    int b = gpos >> 12;
    int hw = gpos & 4095;

    const float* xp = x + (size_t)b * CIN * 4096 + hw + (size_t)cq * 64 * 4096;
    float acc[CO];
#pragma unroll
    for (int o = 0; o < CO; o++) acc[o] = 0.0f;
#pragma unroll 8
    for (int c = 0; c < 64; c++) {
        float xv = xp[(size_t)c * 4096];
        const float* wr = &ws[(cq * 64 + c)];
#pragma unroll
        for (int o = 0; o < CO; o++) acc[o] = fmaf(xv, wr[o * CIN], acc[o]);
    }
#pragma unroll
    for (int o = 0; o < CO; o++) red[cq][pos_local][o] = acc[o];
    __syncthreads();

    for (int i = t; i < 64 * CO; i += 256) {
        int pl = i >> 3, o = i & 7;
        float v = red[0][pl][o] + red[1][pl][o] + red[2][pl][o] + red[3][pl][o] + sb[o];
        int gp = blockIdx.x * 64 + pl;
        int bb = gp >> 12, hw2 = gp & 4095;
        g_y[(size_t)bb * CO * 4096 + (size_t)o * 4096 + hw2] = v;
    }
}

// ---------------------------------------------------------------------------
__device__ __forceinline__ void lerp_coef(int s, int& lo, int& hi, float& f) {
    float pos = (s == SS - 1) ? (float)(HH - 1)
                              : (float)s * ((float)(HH - 1) / (float)(SS - 1));
    lo = (int)pos;
    f = pos - (float)lo;
    hi = lo + 1;
    if (hi > HH - 1) hi = HH - 1;
}
__device__ __forceinline__ float bilerp(const float* __restrict__ yc,
                                        int sl, int sh, float sf,
                                        int tl, int th, float tf) {
    float v0 = yc[sl * HH + tl] * (1.0f - tf) + yc[sl * HH + th] * tf;
    float v1 = yc[sh * HH + tl] * (1.0f - tf) + yc[sh * HH + th] * tf;
    return v0 * (1.0f - sf) + v1 * sf;
}

// ---------------------------------------------------------------------------
// K2: upsample -> argmax -> 4x4 mean pool of onehot
// ---------------------------------------------------------------------------
__global__ void k_fm() {
    int idx = blockIdx.x * blockDim.x + threadIdx.x;
    int b = idx >> 14;
    int ij = idx & 16383;
    int i = ij >> 7, j = ij & 127;
    int cnt[CO];
#pragma unroll
    for (int c = 0; c < CO; c++) cnt[c] = 0;
    const float* yb = g_y + (size_t)b * CO * 4096;
#pragma unroll
    for (int di = 0; di < 4; di++) {
        int s = i * 4 + di;
        int sl, sh; float sf; lerp_coef(s, sl, sh, sf);
#pragma unroll
        for (int dj = 0; dj < 4; dj++) {
            int t = j * 4 + dj;
            int tl, th; float tf; lerp_coef(t, tl, th, tf);
            float best = -1e30f; int bi = 0;
#pragma unroll
            for (int c = 0; c < CO; c++) {
                float v = bilerp(yb + c * 4096, sl, sh, sf, tl, th, tf);
                if (v > best) { best = v; bi = c; }
            }
            cnt[bi]++;
        }
    }
    float* fp = g_fm + (size_t)b * CO * 16384 + ij;
#pragma unroll
    for (int c = 0; c < CO; c++) fp[(size_t)c * 16384] = (float)cnt[c] * (1.0f / 16.0f);
}

// ---------------------------------------------------------------------------
// K3: mma.sync bf16 GEMM (TN). One CTA = (bc, 128-q tile): D[128x64], K=256.
// A split hi+lo bf16 in smem (row-major, padded stride), B exact bf16.
// 8 warps: 4 along M (32 rows each) x 2 along N (32 cols each).
// Fused: nz-count, att copy-out, 1/(nz+1e-5) scaling.
// ---------------------------------------------------------------------------
#define ASTRIDE 264          // 256 + 8 bf16 pad (16B) -> ldmatrix conflict-free
#define SM_AHI_OFF 0
#define SM_ALO_OFF (128 * ASTRIDE)
#define SM_B_OFF   (256 * ASTRIDE)
#define SM_ELEMS   (256 * ASTRIDE + 64 * ASTRIDE)
#define SM_BYTES   (SM_ELEMS * 2)

__device__ __forceinline__ uint32_t smem_u32(const void* p) {
    uint32_t a;
    asm("{ .reg .u64 t; cvta.to.shared.u64 t, %1; cvt.u32.u64 %0, t; }"
        : "=r"(a) : "l"(p));
    return a;
}
__device__ __forceinline__ void ldsm_x4(uint32_t& r0, uint32_t& r1,
                                        uint32_t& r2, uint32_t& r3, uint32_t addr) {
    asm volatile("ldmatrix.sync.aligned.m8n8.x4.shared.b16 {%0,%1,%2,%3}, [%4];"
                 : "=r"(r0), "=r"(r1), "=r"(r2), "=r"(r3) : "r"(addr));
}
__device__ __forceinline__ void mma16816(float* d, uint32_t a0, uint32_t a1,
                                         uint32_t a2, uint32_t a3,
                                         uint32_t b0, uint32_t b1) {
    asm volatile("mma.sync.aligned.m16n8k16.row.col.f32.bf16.bf16.f32 "
                 "{%0,%1,%2,%3}, {%4,%5,%6,%7}, {%8,%9}, {%0,%1,%2,%3};"
                 : "+f"(d[0]), "+f"(d[1]), "+f"(d[2]), "+f"(d[3])
                 : "r"(a0), "r"(a1), "r"(a2), "r"(a3), "r"(b0), "r"(b1));
}

__global__ void __launch_bounds__(256, 1) k_gemm(const float* __restrict__ att,
                                                 float* __restrict__ att_out,
                                                 int do_copy) {
    extern __shared__ __align__(16) __nv_bfloat16 sm[];
    __shared__ int s_cnt[128];
    __shared__ float s_scale[128];

    int t = threadIdx.x;
    int wid = t >> 5, lane = t & 31;
    int q0 = blockIdx.x * 128;
    int bc = blockIdx.y;

    if (t < 128) s_cnt[t] = 0;
    __syncthreads();

    const float* Ab = att + (size_t)bc * QQ * KK + (size_t)q0 * KK;
    float*       Ob = att_out + (size_t)bc * QQ * KK + (size_t)q0 * KK;
    const float* Fb = g_fm + (size_t)bc * 16384;

    __nv_bfloat16* Ahi = sm + SM_AHI_OFF;
    __nv_bfloat16* Alo = sm + SM_ALO_OFF;
    __nv_bfloat16* Bs  = sm + SM_B_OFF;

    // ---- load A (128x256 f32) -> bf16 hi/lo smem; count nz; copy out ----
#pragma unroll 4
    for (int i = 0; i < 32; i++) {
        int idx = i * 256 + t;
        int r = idx >> 6;                 // uniform per warp
        int c4 = (idx & 63) << 2;
        size_t go = (size_t)r * KK + c4;
        float4 v = *(const float4*)(Ab + go);
        if (do_copy) *(float4*)(Ob + go) = v;

        int nz = (v.x != 0.0f) + (v.y != 0.0f) + (v.z != 0.0f) + (v.w != 0.0f);
        nz += __shfl_xor_sync(0xffffffffu, nz, 16);
        nz += __shfl_xor_sync(0xffffffffu, nz, 8);
        nz += __shfl_xor_sync(0xffffffffu, nz, 4);
        nz += __shfl_xor_sync(0xffffffffu, nz, 2);
        nz += __shfl_xor_sync(0xffffffffu, nz, 1);
        if (lane == 0) atomicAdd(&s_cnt[r], nz);

        __nv_bfloat162 h01, h23, l01, l23;
        h01.x = __float2bfloat16_rn(v.x); h01.y = __float2bfloat16_rn(v.y);
        h23.x = __float2bfloat16_rn(v.z); h23.y = __float2bfloat16_rn(v.w);
        l01.x = __float2bfloat16_rn(v.x - __bfloat162float(h01.x));
        l01.y = __float2bfloat16_rn(v.y - __bfloat162float(h01.y));
        l23.x = __float2bfloat16_rn(v.z - __bfloat162float(h23.x));
        l23.y = __float2bfloat16_rn(v.w - __bfloat162float(h23.y));

        *(uint2*)&Ahi[r * ASTRIDE + c4] = make_uint2(*(uint32_t*)&h01, *(uint32_t*)&h23);
        *(uint2*)&Alo[r * ASTRIDE + c4] = make_uint2(*(uint32_t*)&l01, *(uint32_t*)&l23);
    }

    // ---- fill B: Bs[p][k] = unf[p][k] (exact in bf16) ----
#pragma unroll
    for (int i = 0; i < 64; i++) {
        int e = i * 256 + t;              // 16384 elems
        int p = e >> 8, k = e & 255;
        float v = Fb[((k >> 4) * 8 + (p >> 3)) * 128 + (k & 15) * 8 + (p & 7)];
        Bs[p * ASTRIDE + k] = __float2bfloat16_rn(v);
    }
    __syncthreads();

    if (t < 128) s_scale[t] = 1.0f / ((float)s_cnt[t] + 1e-5f);
    __syncthreads();

    // ---- warp tiling: warp_m = wid>>1 (32 rows), warp_n = wid&1 (32 cols) ----
    int m_base = (wid >> 1) * 32;         // q rows this warp
    int n_base = (wid & 1) * 32;          // p cols this warp

    float acc[2][4][4];
#pragma unroll
    for (int mt = 0; mt < 2; mt++)
#pragma unroll
        for (int nt = 0; nt < 4; nt++)
#pragma unroll
            for (int e = 0; e < 4; e++) acc[mt][nt][e] = 0.0f;

    // ldmatrix lane addressing
    // A x4 (m16 x k16): lane l -> row m0 + (l & 15), col k0 + ((l >> 4) << 3)
    int a_row = lane & 15;
    int a_kof = (lane >> 4) << 3;
    // B x4 (two n8 x k16 tiles): lane l -> n = n0 + ((l>>4)<<3) + (l&7),
    //                                     k = k0 + (l & 8)
    int b_n = ((lane >> 4) << 3) + (lane & 7);
    int b_kof = lane & 8;

    uint32_t ahi_base = smem_u32(Ahi);
    uint32_t alo_base = smem_u32(Alo);
    uint32_t b_base   = smem_u32(Bs);

#pragma unroll 4
    for (int ks = 0; ks < 16; ks++) {
        int k0 = ks * 16;
        // B frags: 4 n8-tiles via 2 x4 loads
        uint32_t b0[2], b1[2], b2[2], b3[2];
        {
            uint32_t addr = b_base + (uint32_t)((n_base + b_n) * ASTRIDE + k0 + b_kof) * 2u;
            ldsm_x4(b0[0], b0[1], b1[0], b1[1], addr);
            addr = b_base + (uint32_t)((n_base + 16 + b_n) * ASTRIDE + k0 + b_kof) * 2u;
            ldsm_x4(b2[0], b2[1], b3[0], b3[1], addr);
        }
        // hi pass
#pragma unroll
        for (int mt = 0; mt < 2; mt++) {
            uint32_t a0, a1, a2, a3;
            uint32_t addr = ahi_base +
                (uint32_t)((m_base + mt * 16 + a_row) * ASTRIDE + k0 + a_kof) * 2u;
            ldsm_x4(a0, a1, a2, a3, addr);
            mma16816(acc[mt][0], a0, a1, a2, a3, b0[0], b0[1]);
            mma16816(acc[mt][1], a0, a1, a2, a3, b1[0], b1[1]);
            mma16816(acc[mt][2], a0, a1, a2, a3, b2[0], b2[1]);
            mma16816(acc[mt][3], a0, a1, a2, a3, b3[0], b3[1]);
        }
        // lo pass
#pragma unroll
        for (int mt = 0; mt < 2; mt++) {
            uint32_t a0, a1, a2, a3;
            uint32_t addr = alo_base +
                (uint32_t)((m_base + mt * 16 + a_row) * ASTRIDE + k0 + a_kof) * 2u;
            ldsm_x4(a0, a1, a2, a3, addr);
            mma16816(acc[mt][0], a0, a1, a2, a3, b0[0], b0[1]);
            mma16816(acc[mt][1], a0, a1, a2, a3, b1[0], b1[1]);
            mma16816(acc[mt][2], a0, a1, a2, a3, b2[0], b2[1]);
            mma16816(acc[mt][3], a0, a1, a2, a3, b3[0], b3[1]);
        }
    }

    // ---- epilogue: scale by 1/(nz+eps), store float2 per (row, n8) ----
    float* Cb = g_corr + (size_t)bc * QQ * P2 + (size_t)q0 * P2;
    int gr = lane >> 2;                   // row group 0..7
    int gc = (lane & 3) * 2;              // col pair base
#pragma unroll
    for (int mt = 0; mt < 2; mt++) {
#pragma unroll
        for (int half = 0; half < 2; half++) {
            int row = m_base + mt * 16 + gr + half * 8;
            float sc = s_scale[row];
            float* rowp = Cb + (size_t)row * P2;
#pragma unroll
            for (int nt = 0; nt < 4; nt++) {
                int col = n_base + nt * 8 + gc;
                float2 v = make_float2(acc[mt][nt][half * 2] * sc,
                                       acc[mt][nt][half * 2 + 1] * sc);
                *(float2*)(rowp + col) = v;
            }
        }
    }
}

// ---------------------------------------------------------------------------
// K4: out = log_softmax_c( (corr+1) * y_up )
// ---------------------------------------------------------------------------
__global__ void k_out(float* __restrict__ out) {
    int idx = blockIdx.x * blockDim.x + threadIdx.x;
    int b = idx >> 18;
    int st = idx & 262143;
    int s = st >> 9, t = st & 511;
    int sl, sh; float sf; lerp_coef(s, sl, sh, sf);
    int tl, th; float tf; lerp_coef(t, tl, th, tf);
    int q = (s >> 3) * 64 + (t >> 3);
    int p = (s & 7) * 8 + (t & 7);

    const float* yb = g_y + (size_t)b * CO * 4096;
    const float* cb = g_corr + (size_t)(b * CO) * QQ * P2 + (size_t)q * P2 + p;

    float logit[CO];
    float mx = -1e30f;
#pragma unroll
    for (int c = 0; c < CO; c++) {
        float yv = bilerp(yb + c * 4096, sl, sh, sf, tl, th, tf);
        float corrv = cb[(size_t)c * QQ * P2];
        float l = (corrv + 1.0f) * yv;
        logit[c] = l;
        mx = fmaxf(mx, l);
    }
    float sum = 0.0f;
#pragma unroll
    for (int c = 0; c < CO; c++) sum += __expf(logit[c] - mx);
    float lse = mx + __logf(sum);
    float* op = out + (size_t)b * CO * 262144 + st;
#pragma unroll
    for (int c = 0; c < CO; c++) op[(size_t)c * 262144] = logit[c] - lse;
}

// ---------------------------------------------------------------------------
extern "C" void kernel_launch(void* const* d_in, const int* in_sizes, int n_in,
                              void* d_out, int out_size) {
    const float* x    = (const float*)d_in[0];
    const float* att  = (const float*)d_in[1];
    const float* w    = (const float*)d_in[2];
    const float* bias = (const float*)d_in[3];
    float* out = (float*)d_out;

    const int OUT_ELEMS = BB * CO * SS * SS;   // 8388608
    const int ATT_ELEMS = BB * CO * QQ * KK;   // 33554432
    int do_copy = (out_size >= OUT_ELEMS + ATT_ELEMS) ? 1 : 0;
    float* att_out = out + OUT_ELEMS;

    cudaFuncSetAttribute(k_gemm, cudaFuncAttributeMaxDynamicSharedMemorySize, SM_BYTES);

    k_conv<<<BB * HH * HH / 64, 256>>>(x, w, bias);
    k_fm<<<BB * SMDIM * SMDIM / 256, 256>>>();
    k_gemm<<<dim3(QQ / 128, BB * CO), 256, SM_BYTES>>>(att, att_out, do_copy);
    k_out<<<BB * SS * SS / 256, 256>>>(out);
}

// round 12
// speedup vs baseline: 1.8457x; 1.3077x over previous
#include <cuda_runtime.h>
#include <cuda_bf16.h>
#include <cstdint>

#define BB 4
#define CIN 256
#define CO 8
#define HH 64          // input spatial
#define SS 512         // resize_shape
#define SMDIM 128      // pooled spatial
#define QQ 4096
#define P2 64
#define KK 256

__device__ float g_y[BB * CO * HH * HH];
__device__ __nv_bfloat16 g_unf[BB * CO * P2 * KK];   // [bc][p][k], exact bf16, 1 MB
__device__ float g_corr[BB * CO * QQ * P2];

// ---------------------------------------------------------------------------
// K1: 1x1 conv
// ---------------------------------------------------------------------------
__global__ void k_conv(const float* __restrict__ x, const float* __restrict__ w,
                       const float* __restrict__ bias) {
    __shared__ float ws[CO * CIN];
    __shared__ float sb[CO];
    __shared__ float red[4][64][CO];
    for (int i = threadIdx.x; i < CO * CIN; i += blockDim.x) ws[i] = w[i];
    if (threadIdx.x < CO) sb[threadIdx.x] = bias[threadIdx.x];
    __syncthreads();

    int t = threadIdx.x;
    int pos_local = t & 63;
    int cq = t >> 6;
    int gpos = blockIdx.x * 64 + pos_local;
    int b = gpos >> 12;
    int hw = gpos & 4095;

    const float* xp = x + (size_t)b * CIN * 4096 + hw + (size_t)cq * 64 * 4096;
    float acc[CO];
#pragma unroll
    for (int o = 0; o < CO; o++) acc[o] = 0.0f;
#pragma unroll 8
    for (int c = 0; c < 64; c++) {
        float xv = xp[(size_t)c * 4096];
        const float* wr = &ws[(cq * 64 + c)];
#pragma unroll
        for (int o = 0; o < CO; o++) acc[o] = fmaf(xv, wr[o * CIN], acc[o]);
    }
#pragma unroll
    for (int o = 0; o < CO; o++) red[cq][pos_local][o] = acc[o];
    __syncthreads();

    for (int i = t; i < 64 * CO; i += 256) {
        int pl = i >> 3, o = i & 7;
        float v = red[0][pl][o] + red[1][pl][o] + red[2][pl][o] + red[3][pl][o] + sb[o];
        int gp = blockIdx.x * 64 + pl;
        int bb = gp >> 12, hw2 = gp & 4095;
        g_y[(size_t)bb * CO * 4096 + (size_t)o * 4096 + hw2] = v;
    }
}

// ---------------------------------------------------------------------------
__device__ __forceinline__ void lerp_coef(int s, int& lo, int& hi, float& f) {
    float pos = (s == SS - 1) ? (float)(HH - 1)
                              : (float)s * ((float)(HH - 1) / (float)(SS - 1));
    lo = (int)pos;
    f = pos - (float)lo;
    hi = lo + 1;
    if (hi > HH - 1) hi = HH - 1;
}
__device__ __forceinline__ float bilerp(const float* __restrict__ yc,
                                        int sl, int sh, float sf,
                                        int tl, int th, float tf) {
    float v0 = yc[sl * HH + tl] * (1.0f - tf) + yc[sl * HH + th] * tf;
    float v1 = yc[sh * HH + tl] * (1.0f - tf) + yc[sh * HH + th] * tf;
    return v0 * (1.0f - sf) + v1 * sf;
}

// ---------------------------------------------------------------------------
// K2: upsample -> argmax -> 4x4 mean pool of onehot -> write unf layout (bf16)
// unf[p][k] with k = (i>>3)*16 + (j>>3), p = (i&7)*8 + (j&7)
// ---------------------------------------------------------------------------
__global__ void k_fm() {
    int idx = blockIdx.x * blockDim.x + threadIdx.x;
    int b = idx >> 14;
    int ij = idx & 16383;
    int i = ij >> 7, j = ij & 127;
    int cnt[CO];
#pragma unroll
    for (int c = 0; c < CO; c++) cnt[c] = 0;
    const float* yb = g_y + (size_t)b * CO * 4096;
#pragma unroll
    for (int di = 0; di < 4; di++) {
        int s = i * 4 + di;
        int sl, sh; float sf; lerp_coef(s, sl, sh, sf);
#pragma unroll
        for (int dj = 0; dj < 4; dj++) {
            int t = j * 4 + dj;
            int tl, th; float tf; lerp_coef(t, tl, th, tf);
            float best = -1e30f; int bi = 0;
#pragma unroll
            for (int c = 0; c < CO; c++) {
                float v = bilerp(yb + c * 4096, sl, sh, sf, tl, th, tf);
                if (v > best) { best = v; bi = c; }
            }
            cnt[bi]++;
        }
    }
    int k = (i >> 3) * 16 + (j >> 3);
    int p = (i & 7) * 8 + (j & 7);
    __nv_bfloat16* up = g_unf + (((size_t)b * CO) << 14) + (p << 8) + k;
#pragma unroll
    for (int c = 0; c < CO; c++)
        up[(size_t)c << 14] = __float2bfloat16_rn((float)cnt[c] * (1.0f / 16.0f));
}

// ---------------------------------------------------------------------------
// K3: mma.sync bf16 GEMM (TN). One CTA = (bc, 64-q tile): D[64x64], K=256.
// 101 KB smem -> 2 CTAs/SM co-resident (load of one overlaps MMA of other).
// A split hi+lo bf16; B = g_unf copied coalesced. Fused nz-count + copy-out.
// ---------------------------------------------------------------------------
#define TQ 64
#define ASTRIDE 264          // 256 + 8 bf16 pad -> ldmatrix conflict-free
#define SM_AHI_OFF 0
#define SM_ALO_OFF (TQ * ASTRIDE)
#define SM_B_OFF   (2 * TQ * ASTRIDE)
#define SM_ELEMS   (3 * TQ * ASTRIDE)
#define SM_BYTES   (SM_ELEMS * 2)

__device__ __forceinline__ uint32_t smem_u32(const void* p) {
    uint32_t a;
    asm("{ .reg .u64 t; cvta.to.shared.u64 t, %1; cvt.u32.u64 %0, t; }"
        : "=r"(a) : "l"(p));
    return a;
}
__device__ __forceinline__ void ldsm_x4(uint32_t& r0, uint32_t& r1,
                                        uint32_t& r2, uint32_t& r3, uint32_t addr) {
    asm volatile("ldmatrix.sync.aligned.m8n8.x4.shared.b16 {%0,%1,%2,%3}, [%4];"
                 : "=r"(r0), "=r"(r1), "=r"(r2), "=r"(r3) : "r"(addr));
}
__device__ __forceinline__ void mma16816(float* d, uint32_t a0, uint32_t a1,
                                         uint32_t a2, uint32_t a3,
                                         uint32_t b0, uint32_t b1) {
    asm volatile("mma.sync.aligned.m16n8k16.row.col.f32.bf16.bf16.f32 "
                 "{%0,%1,%2,%3}, {%4,%5,%6,%7}, {%8,%9}, {%0,%1,%2,%3};"
                 : "+f"(d[0]), "+f"(d[1]), "+f"(d[2]), "+f"(d[3])
                 : "r"(a0), "r"(a1), "r"(a2), "r"(a3), "r"(b0), "r"(b1));
}

__global__ void __launch_bounds__(256, 2) k_gemm(const float* __restrict__ att,
                                                 float* __restrict__ att_out,
                                                 int do_copy) {
    extern __shared__ __align__(16) __nv_bfloat16 sm[];
    __shared__ int s_cnt[TQ];
    __shared__ float s_scale[TQ];

    int t = threadIdx.x;
    int wid = t >> 5, lane = t & 31;
    int q0 = blockIdx.x * TQ;
    int bc = blockIdx.y;

    if (t < TQ) s_cnt[t] = 0;
    __syncthreads();

    const float* Ab = att + (size_t)bc * QQ * KK + (size_t)q0 * KK;
    float*       Ob = att_out + (size_t)bc * QQ * KK + (size_t)q0 * KK;

    __nv_bfloat16* Ahi = sm + SM_AHI_OFF;
    __nv_bfloat16* Alo = sm + SM_ALO_OFF;
    __nv_bfloat16* Bs  = sm + SM_B_OFF;

    // ---- B fill: coalesced uint4 copy from g_unf (L2-resident), 8 iters ----
    const __nv_bfloat16* Ub = g_unf + ((size_t)bc << 14);
#pragma unroll
    for (int i = 0; i < 8; i++) {
        int idx = i * 256 + t;
        int p = idx >> 5;
        int k8 = (idx & 31) << 3;
        *(uint4*)&Bs[p * ASTRIDE + k8] = *(const uint4*)&Ub[(p << 8) + k8];
    }

    // ---- load A (64x256 f32) -> bf16 hi/lo smem; count nz; copy out ----
#pragma unroll 4
    for (int i = 0; i < 16; i++) {
        int idx = i * 256 + t;
        int r = idx >> 6;                 // uniform per warp
        int c4 = (idx & 63) << 2;
        size_t go = (size_t)r * KK + c4;
        float4 v = *(const float4*)(Ab + go);
        if (do_copy) *(float4*)(Ob + go) = v;

        int nz = (v.x != 0.0f) + (v.y != 0.0f) + (v.z != 0.0f) + (v.w != 0.0f);
        nz += __shfl_xor_sync(0xffffffffu, nz, 16);
        nz += __shfl_xor_sync(0xffffffffu, nz, 8);
        nz += __shfl_xor_sync(0xffffffffu, nz, 4);
        nz += __shfl_xor_sync(0xffffffffu, nz, 2);
        nz += __shfl_xor_sync(0xffffffffu, nz, 1);
        if (lane == 0) atomicAdd(&s_cnt[r], nz);

        __nv_bfloat162 h01, h23, l01, l23;
        h01.x = __float2bfloat16_rn(v.x); h01.y = __float2bfloat16_rn(v.y);
        h23.x = __float2bfloat16_rn(v.z); h23.y = __float2bfloat16_rn(v.w);
        l01.x = __float2bfloat16_rn(v.x - __bfloat162float(h01.x));
        l01.y = __float2bfloat16_rn(v.y - __bfloat162float(h01.y));
        l23.x = __float2bfloat16_rn(v.z - __bfloat162float(h23.x));
        l23.y = __float2bfloat16_rn(v.w - __bfloat162float(h23.y));

        *(uint2*)&Ahi[r * ASTRIDE + c4] = make_uint2(*(uint32_t*)&h01, *(uint32_t*)&h23);
        *(uint2*)&Alo[r * ASTRIDE + c4] = make_uint2(*(uint32_t*)&l01, *(uint32_t*)&l23);
    }
    __syncthreads();

    if (t < TQ) s_scale[t] = 1.0f / ((float)s_cnt[t] + 1e-5f);
    __syncthreads();

    // ---- warp tiling: 4 warps along M (16 rows), 2 along N (32 cols) ----
    int m_base = (wid >> 1) * 16;
    int n_base = (wid & 1) * 32;

    float acc[4][4];
#pragma unroll
    for (int nt = 0; nt < 4; nt++)
#pragma unroll
        for (int e = 0; e < 4; e++) acc[nt][e] = 0.0f;

    int a_row = lane & 15;
    int a_kof = (lane >> 4) << 3;
    int b_n = ((lane >> 4) << 3) + (lane & 7);
    int b_kof = lane & 8;

    uint32_t ahi_base = smem_u32(Ahi);
    uint32_t alo_base = smem_u32(Alo);
    uint32_t b_base   = smem_u32(Bs);

#pragma unroll 4
    for (int ks = 0; ks < 16; ks++) {
        int k0 = ks * 16;
        uint32_t b0[2], b1[2], b2[2], b3[2];
        {
            uint32_t addr = b_base + (uint32_t)((n_base + b_n) * ASTRIDE + k0 + b_kof) * 2u;
            ldsm_x4(b0[0], b0[1], b1[0], b1[1], addr);
            addr = b_base + (uint32_t)((n_base + 16 + b_n) * ASTRIDE + k0 + b_kof) * 2u;
            ldsm_x4(b2[0], b2[1], b3[0], b3[1], addr);
        }
        {
            uint32_t a0, a1, a2, a3;
            uint32_t addr = ahi_base +
                (uint32_t)((m_base + a_row) * ASTRIDE + k0 + a_kof) * 2u;
            ldsm_x4(a0, a1, a2, a3, addr);
            mma16816(acc[0], a0, a1, a2, a3, b0[0], b0[1]);
            mma16816(acc[1], a0, a1, a2, a3, b1[0], b1[1]);
            mma16816(acc[2], a0, a1, a2, a3, b2[0], b2[1]);
            mma16816(acc[3], a0, a1, a2, a3, b3[0], b3[1]);
        }
        {
            uint32_t a0, a1, a2, a3;
            uint32_t addr = alo_base +
                (uint32_t)((m_base + a_row) * ASTRIDE + k0 + a_kof) * 2u;
            ldsm_x4(a0, a1, a2, a3, addr);
            mma16816(acc[0], a0, a1, a2, a3, b0[0], b0[1]);
            mma16816(acc[1], a0, a1, a2, a3, b1[0], b1[1]);
            mma16816(acc[2], a0, a1, a2, a3, b2[0], b2[1]);
            mma16816(acc[3], a0, a1, a2, a3, b3[0], b3[1]);
        }
    }

    // ---- epilogue: scale by 1/(nz+eps), store float2 per (row, n8) ----
    float* Cb = g_corr + (size_t)bc * QQ * P2 + (size_t)q0 * P2;
    int gr = lane >> 2;
    int gc = (lane & 3) * 2;
#pragma unroll
    for (int half = 0; half < 2; half++) {
        int row = m_base + gr + half * 8;
        float sc = s_scale[row];
        float* rowp = Cb + (size_t)row * P2;
#pragma unroll
        for (int nt = 0; nt < 4; nt++) {
            int col = n_base + nt * 8 + gc;
            float2 v = make_float2(acc[nt][half * 2] * sc,
                                   acc[nt][half * 2 + 1] * sc);
            *(float2*)(rowp + col) = v;
        }
    }
}

// ---------------------------------------------------------------------------
// K4: out = log_softmax_c( (corr+1) * y_up )
// ---------------------------------------------------------------------------
__global__ void k_out(float* __restrict__ out) {
    int idx = blockIdx.x * blockDim.x + threadIdx.x;
    int b = idx >> 18;
    int st = idx & 262143;
    int s = st >> 9, t = st & 511;
    int sl, sh; float sf; lerp_coef(s, sl, sh, sf);
    int tl, th; float tf; lerp_coef(t, tl, th, tf);
    int q = (s >> 3) * 64 + (t >> 3);
    int p = (s & 7) * 8 + (t & 7);

    const float* yb = g_y + (size_t)b * CO * 4096;
    const float* cb = g_corr + (size_t)(b * CO) * QQ * P2 + (size_t)q * P2 + p;

    float logit[CO];
    float mx = -1e30f;
#pragma unroll
    for (int c = 0; c < CO; c++) {
        float yv = bilerp(yb + c * 4096, sl, sh, sf, tl, th, tf);
        float corrv = cb[(size_t)c * QQ * P2];
        float l = (corrv + 1.0f) * yv;
        logit[c] = l;
        mx = fmaxf(mx, l);
    }
    float sum = 0.0f;
#pragma unroll
    for (int c = 0; c < CO; c++) sum += __expf(logit[c] - mx);
    float lse = mx + __logf(sum);
    float* op = out + (size_t)b * CO * 262144 + st;
#pragma unroll
    for (int c = 0; c < CO; c++) op[(size_t)c * 262144] = logit[c] - lse;
}

// ---------------------------------------------------------------------------
extern "C" void kernel_launch(void* const* d_in, const int* in_sizes, int n_in,
                              void* d_out, int out_size) {
    const float* x    = (const float*)d_in[0];
    const float* att  = (const float*)d_in[1];
    const float* w    = (const float*)d_in[2];
    const float* bias = (const float*)d_in[3];
    float* out = (float*)d_out;

    const int OUT_ELEMS = BB * CO * SS * SS;   // 8388608
    const int ATT_ELEMS = BB * CO * QQ * KK;   // 33554432
    int do_copy = (out_size >= OUT_ELEMS + ATT_ELEMS) ? 1 : 0;
    float* att_out = out + OUT_ELEMS;

    cudaFuncSetAttribute(k_gemm, cudaFuncAttributeMaxDynamicSharedMemorySize, SM_BYTES);

    k_conv<<<BB * HH * HH / 64, 256>>>(x, w, bias);
    k_fm<<<BB * SMDIM * SMDIM / 256, 256>>>();
    k_gemm<<<dim3(QQ / TQ, BB * CO), 256, SM_BYTES>>>(att, att_out, do_copy);
    k_out<<<BB * SS * SS / 256, 256>>>(out);
}